// round 12
// baseline (speedup 1.0000x reference)
#include <cuda_runtime.h>
#include <cuda_fp16.h>
#include <math.h>
#include <stdint.h>

#define B_ 8192
#define D_ 128
#define NT_ 64                            // number of 128-row tiles
#define NPAIRS ((NT_ * (NT_ + 1)) / 2)    // 2080 upper-triangular tile pairs
#define GRID_ 296                         // 2 persistent CTAs per SM (all resident)

// Smem tiles: 128 rows x 128 halves (256B) padded to 272B (stride ≡ 16 mod 128
// => ldmatrix 8-row groups hit banks conflict-free). Single tile buffer,
// prefetched in place; q codes double-buffered (epilogue overlap).
#define ROWB 272
#define TILE_BYTES (128 * ROWB)           // 34816
#define OFF_A 0
#define OFF_B TILE_BYTES
#define OFF_Q  (2 * TILE_BYTES)           // q[2][256] floats
#define SMEM_BYTES (OFF_Q + 2 * 256 * 4)  // 71680 (x2 CTAs = 143360 <= 228KB)

__device__ __align__(16) __half g_eH[B_ * D_];  // scaled by sqrt(log2e/T), fp16
__device__ float g_q[B_];    // class code: sign(conf) * (label==1 ? 1 : 2)
__device__ float g_pos[B_];
__device__ float g_neg[B_];
__device__ unsigned long long g_bar = 0;   // monotonic grid-barrier ticket

// ---------------------------------------------------------------------------
__device__ __forceinline__ uint32_t smem_u32(const void* p) {
    uint32_t a;
    asm("{ .reg .u64 t; cvta.to.shared.u64 t, %1; cvt.u32.u64 %0, t; }" : "=r"(a) : "l"(p));
    return a;
}
__device__ __forceinline__ __half2 h2ex2(__half2 x) {
    __half2 y;
    asm("ex2.approx.f16x2 %0, %1;"
        : "=r"(*reinterpret_cast<uint32_t*>(&y))
        : "r"(*reinterpret_cast<uint32_t*>(&x)));
    return y;
}
__device__ __forceinline__ void cpasync16(uint32_t saddr, const void* g) {
    asm volatile("cp.async.cg.shared.global [%0], [%1], 16;" :: "r"(saddr), "l"(g));
}
#define CP_COMMIT() asm volatile("cp.async.commit_group;" ::: "memory")
#define CP_WAIT0()  asm volatile("cp.async.wait_group 0;" ::: "memory")

__device__ __forceinline__ void ldm_x4(uint32_t* r, uint32_t addr) {
    asm volatile("ldmatrix.sync.aligned.m8n8.x4.shared.b16 {%0,%1,%2,%3}, [%4];"
                 : "=r"(r[0]), "=r"(r[1]), "=r"(r[2]), "=r"(r[3]) : "r"(addr));
}
__device__ __forceinline__ void mma_f16acc(uint32_t* d, const uint32_t* a, const uint32_t* b) {
    asm volatile(
        "mma.sync.aligned.m16n8k16.row.col.f16.f16.f16.f16 "
        "{%0,%1}, {%2,%3,%4,%5}, {%6,%7}, {%0,%1};"
        : "+r"(d[0]), "+r"(d[1])
        : "r"(a[0]), "r"(a[1]), "r"(a[2]), "r"(a[3]), "r"(b[0]), "r"(b[1]));
}

// Triangular decode: idx -> (ti, tj), ti <= tj. Float sqrt + exact fixups.
#define FTRI(i) ((i) * (2 * NT_ - (i) + 1) / 2)
__device__ __forceinline__ void tri_decode(int idx, int& ti, int& tj) {
    float f = 2.f * NT_ + 1.f;
    int t = (int)((f - sqrtf(fmaxf(f * f - 8.f * (float)idx, 0.f))) * 0.5f);
    if (t < 0) t = 0;
    if (t > NT_ - 1) t = NT_ - 1;
    while (t > 0 && FTRI(t) > idx) t--;
    while (FTRI(t + 1) <= idx) t++;
    ti = t;
    tj = t + (idx - FTRI(t));
}

// Monotonic-ticket grid barrier. Safe: all GRID_ CTAs are co-resident
// (grid == guaranteed occupancy), counter never resets (replay-safe).
__device__ __forceinline__ void grid_barrier(int tid) {
    __syncthreads();
    if (tid == 0) {
        __threadfence();
        unsigned long long ticket = atomicAdd(&g_bar, 1ULL);
        unsigned long long target = (ticket / GRID_ + 1ULL) * GRID_;
        unsigned long long v;
        do {
            asm volatile("ld.global.acquire.gpu.u64 %0, [%1];" : "=l"(v) : "l"(&g_bar));
        } while (v < target);
    }
    __syncthreads();
}

// ---------------------------------------------------------------------------
// Fused kernel: phase 0 = prep, barrier, phase 1 = sim tiles, barrier,
// phase 2 = final loss reduce (CTA 0).
// ---------------------------------------------------------------------------
__global__ void __launch_bounds__(512, 2) fused_kernel(
    const float* __restrict__ emb,
    const int*   __restrict__ labels,
    const float* __restrict__ conf,
    float* __restrict__ out
) {
    extern __shared__ char smem[];
    const uint32_t sb = smem_u32(smem);

    const int tid  = threadIdx.x;
    const int wid  = tid >> 5;
    const int lane = tid & 31;
    const int grp  = lane >> 2;     // 0..7
    const int qid  = lane & 3;      // 0..3
    const int wr   = wid >> 2;      // warp row
    const int wc   = wid & 3;       // warp col

    // ---------------- Phase 0: prep ----------------
    // 16 threads per row, each loads 2 float4 (MLP 2). 8192 rows total.
    {
        int gt  = blockIdx.x * 512 + tid;
        int row = gt >> 4;
        int seg = gt & 15;
        if (row < B_) {
            const float4* src = (const float4*)(emb + (size_t)row * D_);
            float4 v0 = src[seg];
            float4 v1 = src[seg + 16];
            float ss = v0.x*v0.x + v0.y*v0.y + v0.z*v0.z + v0.w*v0.w
                     + v1.x*v1.x + v1.y*v1.y + v1.z*v1.z + v1.w*v1.w;
            ss += __shfl_xor_sync(0xffffffffu, ss, 1);
            ss += __shfl_xor_sync(0xffffffffu, ss, 2);
            ss += __shfl_xor_sync(0xffffffffu, ss, 4);
            ss += __shfl_xor_sync(0xffffffffu, ss, 8);
            const float SCALE = 3.7982826f;   // sqrt(log2(e) / 0.1)
            float s = SCALE / fmaxf(sqrtf(ss), 1e-12f);
            __half2 a0 = __floats2half2_rn(v0.x * s, v0.y * s);
            __half2 a1 = __floats2half2_rn(v0.z * s, v0.w * s);
            __half2 b0 = __floats2half2_rn(v1.x * s, v1.y * s);
            __half2 b1 = __floats2half2_rn(v1.z * s, v1.w * s);
            uint2 p0 = { *(uint32_t*)&a0, *(uint32_t*)&a1 };
            uint2 p1 = { *(uint32_t*)&b0, *(uint32_t*)&b1 };
            uint2* dst = (uint2*)(g_eH + (size_t)row * D_);
            dst[seg]      = p0;
            dst[seg + 16] = p1;
            if (seg == 0) {
                float c = conf[row];
                float sg = (c > 0.f) ? 1.f : ((c < 0.f) ? -1.f : 0.f);
                g_q[row] = sg * ((labels[row] == 1) ? 1.f : 2.f);
                g_pos[row] = 0.f;
                g_neg[row] = 0.f;
            }
        }
    }

    grid_barrier(tid);

    // ---------------- Phase 1: sim tiles (exact R9 structure) ----------------
    float* qsm = (float*)(smem + OFF_Q);   // [2][256]

    const uint32_t aAddr0 = sb + OFF_A + (uint32_t)((wr * 32 + (lane & 15)) * ROWB)
                          + (uint32_t)((lane >> 4) * 16);
    const uint32_t bAddr0 = sb + OFF_B + (uint32_t)((wc * 32 + ((lane >> 4) & 1) * 8 + (lane & 7)) * ROWB)
                          + (uint32_t)(((lane >> 3) & 1) * 16);

    const __half2 ONE2  = __float2half2_rn(1.f);
    const __half2 TWO2  = __float2half2_rn(2.f);
    const __half2 FOUR2 = __float2half2_rn(4.f);

    auto issue_fill = [&](int ti, int tj, int qb) {
        const char* srcA = (const char*)(g_eH + (size_t)(ti * 128) * D_);
        const char* srcB = (const char*)(g_eH + (size_t)(tj * 128) * D_);
        #pragma unroll
        for (int it = 0; it < 4; it++) {
            int tt = tid + it * 512;         // 0..2047
            int row = tt >> 4, kg = tt & 15; // 16B group within 256B row
            uint32_t doff = (uint32_t)(row * ROWB + kg * 16);
            size_t soff = (size_t)row * 256 + (size_t)kg * 16;
            cpasync16(sb + OFF_A + doff, srcA + soff);
            cpasync16(sb + OFF_B + doff, srcB + soff);
        }
        CP_COMMIT();
        if (tid < 128)       qsm[qb * 256 + tid] = g_q[ti * 128 + tid];
        else if (tid < 256)  qsm[qb * 256 + tid] = g_q[tj * 128 + (tid - 128)];
    };

    {
        int ti0, tj0;
        tri_decode(blockIdx.x, ti0, tj0);
        issue_fill(ti0, tj0, 0);
    }

    int qb = 0;
    for (int t = blockIdx.x; t < NPAIRS; t += GRID_) {
        int ti, tj;
        tri_decode(t, ti, tj);
        const int i0 = ti * 128;
        const int j0 = tj * 128;
        const bool offdiag = (ti != tj);

        CP_WAIT0();
        __syncthreads();   // tile t + q codes visible; prev epilogue done

        uint32_t acc[2][4][2] = {};   // [mt][nt][q] half2 accumulators

        #pragma unroll
        for (int ks = 0; ks < 8; ks++) {
            const uint32_t ko = (uint32_t)(ks * 32);   // 16 halves = 32B per kstep
            uint32_t af[2][4], bf[2][4];
            ldm_x4(af[0], aAddr0 + ko);
            ldm_x4(af[1], aAddr0 + (uint32_t)(16 * ROWB) + ko);
            ldm_x4(bf[0], bAddr0 + ko);
            ldm_x4(bf[1], bAddr0 + (uint32_t)(16 * ROWB) + ko);
            #pragma unroll
            for (int mt = 0; mt < 2; mt++)
                #pragma unroll
                for (int nt = 0; nt < 4; nt++)
                    mma_f16acc(acc[mt][nt], af[mt], &bf[nt >> 1][(nt & 1) * 2]);
        }

        __syncthreads();   // all warps done reading tile smem buffers

        // Prefetch next tile in place; lands while the epilogue runs.
        int tn = t + GRID_;
        if (tn < NPAIRS) {
            int tin, tjn;
            tri_decode(tn, tin, tjn);
            issue_fill(tin, tjn, qb ^ 1);
        }

        // ---------------- Epilogue (half2) ----------------
        const float* qi_sh = qsm + qb * 256;       // current tile's q codes
        const float* qj_sh = qi_sh + 128;
        __half2 fih[4], fjh[4];
        #pragma unroll
        for (int mt = 0; mt < 2; mt++) {
            fih[mt * 2 + 0] = __float2half2_rn(qi_sh[wr * 32 + mt * 16 + grp]);
            fih[mt * 2 + 1] = __float2half2_rn(qi_sh[wr * 32 + mt * 16 + grp + 8]);
        }
        #pragma unroll
        for (int nt = 0; nt < 4; nt++) {
            int c0 = wc * 32 + nt * 8 + 2 * qid;
            fjh[nt] = __floats2half2_rn(qj_sh[c0], qj_sh[c0 + 1]);
        }

        __half2 ps2[4], ns2[4], cp2[4], cn2[4];
        #pragma unroll
        for (int k = 0; k < 4; k++) {
            ps2[k] = __float2half2_rn(0.f); ns2[k] = __float2half2_rn(0.f);
            cp2[k] = __float2half2_rn(0.f); cn2[k] = __float2half2_rn(0.f);
        }

        if (offdiag) {
            #pragma unroll
            for (int mt = 0; mt < 2; mt++)
                #pragma unroll
                for (int nt = 0; nt < 4; nt++)
                    #pragma unroll
                    for (int q = 0; q < 2; q++) {
                        __half2 e = h2ex2(*reinterpret_cast<__half2*>(&acc[mt][nt][q]));
                        __half2 p = __hmul2(fih[mt * 2 + q], fjh[nt]);
                        __half2 pos = __hadd2(__heq2(p, ONE2), __heq2(p, FOUR2));
                        __half2 neg = __heq2(p, TWO2);
                        ps2[mt * 2 + q] = __hfma2(e, pos, ps2[mt * 2 + q]);
                        ns2[mt * 2 + q] = __hfma2(e, neg, ns2[mt * 2 + q]);
                        cp2[nt] = __hfma2(e, pos, cp2[nt]);
                        cn2[nt] = __hfma2(e, neg, cn2[nt]);
                    }
        } else {
            // Diagonal tile: kill i==j BEFORE accumulation (self term 2^14.4
            // would swamp fp16 partials); no col sums (tile is its own transpose).
            #pragma unroll
            for (int mt = 0; mt < 2; mt++)
                #pragma unroll
                for (int nt = 0; nt < 4; nt++)
                    #pragma unroll
                    for (int q = 0; q < 2; q++) {
                        int row = wr * 32 + mt * 16 + grp + q * 8;
                        int c0  = wc * 32 + nt * 8 + 2 * qid;
                        __half2 e = h2ex2(*reinterpret_cast<__half2*>(&acc[mt][nt][q]));
                        __half2 p = __hmul2(fih[mt * 2 + q], fjh[nt]);
                        __half2 pos = __hadd2(__heq2(p, ONE2), __heq2(p, FOUR2));
                        __half2 neg = __heq2(p, TWO2);
                        __half2 dk = __floats2half2_rn(row == c0 ? 0.f : 1.f,
                                                       row == c0 + 1 ? 0.f : 1.f);
                        pos = __hmul2(pos, dk);
                        ps2[mt * 2 + q] = __hfma2(e, pos, ps2[mt * 2 + q]);
                        ns2[mt * 2 + q] = __hfma2(e, neg, ns2[mt * 2 + q]);
                    }
        }

        // Row reduce: combine half2 lanes to f32, shfl over qid (xor 1,2).
        float psf[4], nsf[4];
        #pragma unroll
        for (int r = 0; r < 4; r++) {
            float2 a = __half22float2(ps2[r]); psf[r] = a.x + a.y;
            float2 bq = __half22float2(ns2[r]); nsf[r] = bq.x + bq.y;
        }
        #pragma unroll
        for (int r = 0; r < 4; r++) {
            #pragma unroll
            for (int o = 1; o <= 2; o <<= 1) {
                psf[r] += __shfl_xor_sync(0xffffffffu, psf[r], o);
                nsf[r] += __shfl_xor_sync(0xffffffffu, nsf[r], o);
            }
        }
        if (qid == 0) {
            #pragma unroll
            for (int r = 0; r < 4; r++) {
                int gi = i0 + wr * 32 + (r >> 1) * 16 + grp + (r & 1) * 8;
                atomicAdd(&g_pos[gi], psf[r]);
                atomicAdd(&g_neg[gi], nsf[r]);
            }
        }

        // Col reduce (off-diag only): packed half2 shfl over grp (xor 4,8,16).
        if (offdiag) {
            #pragma unroll
            for (int c = 0; c < 4; c++) {
                #pragma unroll
                for (int o = 4; o <= 16; o <<= 1) {
                    uint32_t up = __shfl_xor_sync(0xffffffffu, *reinterpret_cast<uint32_t*>(&cp2[c]), o);
                    uint32_t un = __shfl_xor_sync(0xffffffffu, *reinterpret_cast<uint32_t*>(&cn2[c]), o);
                    cp2[c] = __hadd2(cp2[c], *reinterpret_cast<__half2*>(&up));
                    cn2[c] = __hadd2(cn2[c], *reinterpret_cast<__half2*>(&un));
                }
            }
            if (grp == 0) {
                #pragma unroll
                for (int c = 0; c < 4; c++) {
                    int gj = j0 + wc * 32 + c * 8 + 2 * qid;
                    float2 a = __half22float2(cp2[c]);
                    float2 bq = __half22float2(cn2[c]);
                    atomicAdd(&g_pos[gj],     a.x);
                    atomicAdd(&g_pos[gj + 1], a.y);
                    atomicAdd(&g_neg[gj],     bq.x);
                    atomicAdd(&g_neg[gj + 1], bq.y);
                }
            }
        }

        qb ^= 1;
    }

    grid_barrier(tid);

    // ---------------- Phase 2: final loss reduce (CTA 0) ----------------
    if (blockIdx.x == 0) {
        __shared__ float s1[16], s2[16];
        float tot = 0.f, cnt = 0.f;
        for (int i = tid; i < B_; i += 512) {
            float p = g_pos[i], n = g_neg[i];
            if (p > 0.f && n > 0.f) {
                tot += -__logf(p / (p + n + 1e-8f));
                cnt += 1.f;
            }
        }
        #pragma unroll
        for (int o = 16; o; o >>= 1) {
            tot += __shfl_xor_sync(0xffffffffu, tot, o);
            cnt += __shfl_xor_sync(0xffffffffu, cnt, o);
        }
        if (lane == 0) { s1[wid] = tot; s2[wid] = cnt; }
        __syncthreads();
        if (wid == 0 && lane < 16) {
            tot = s1[lane]; cnt = s2[lane];
            #pragma unroll
            for (int o = 8; o; o >>= 1) {
                tot += __shfl_xor_sync(0xffffu, tot, o);
                cnt += __shfl_xor_sync(0xffffu, cnt, o);
            }
            if (lane == 0) out[0] = (cnt > 0.f) ? (tot / cnt) : 0.f;
        }
    }
}

extern "C" void kernel_launch(void* const* d_in, const int* in_sizes, int n_in,
                              void* d_out, int out_size) {
    const float* emb    = (const float*)d_in[0];
    const int*   labels = (const int*)  d_in[1];
    const float* conf   = (const float*)d_in[2];
    (void)n_in; (void)out_size; (void)in_sizes;

    cudaFuncSetAttribute(fused_kernel, cudaFuncAttributeMaxDynamicSharedMemorySize, SMEM_BYTES);

    fused_kernel<<<GRID_, 512, SMEM_BYTES>>>(emb, labels, conf, (float*)d_out);
}